// round 3
// baseline (speedup 1.0000x reference)
#include <cuda_runtime.h>

// Output is identically zero: g = -sum((x - x)^2) == 0, so w = C*g == 0 and
// lambda_tri = mask @ w == 0. Fastest correct kernel = zero-fill 64 KB.
//
// R1 (16-block kernel) and R2 (memset node) both timed 4.863999 us exactly ->
// we are at the graph-replay floor. This round: single-block, single-SM fill
// (no block-dispatch ramp), 1024 threads x 4 float4 stores = 16384 floats.

__global__ __launch_bounds__(1024, 1)
void zero_one_block(float4* __restrict__ out) {
    int t = threadIdx.x;            // 0..1023
    float4 z = make_float4(0.f, 0.f, 0.f, 0.f);
    // 4096 float4s total; thread t writes t, t+1024, t+2048, t+3072
    out[t]        = z;
    out[t + 1024] = z;
    out[t + 2048] = z;
    out[t + 3072] = z;
}

__global__ void zero_generic(float* __restrict__ out, int n) {
    int i = blockIdx.x * blockDim.x + threadIdx.x;
    if (i < n) out[i] = 0.f;
}

extern "C" void kernel_launch(void* const* d_in, const int* in_sizes, int n_in,
                              void* d_out, int out_size) {
    (void)d_in; (void)in_sizes; (void)n_in;
    if (out_size == 16384) {
        zero_one_block<<<1, 1024>>>((float4*)d_out);
    } else {
        int threads = 256;
        int blocks = (out_size + threads - 1) / threads;
        zero_generic<<<blocks, threads>>>((float*)d_out, out_size);
    }
}

// round 4
// speedup vs baseline: 1.4444x; 1.4444x over previous
#include <cuda_runtime.h>

// Output is identically zero: g = -sum((x - x)^2) == 0 elementwise, so
// w = C*g == 0 and lambda_tri = mask @ w == 0. Kernel = 64 KB zero-fill.
//
// Measurement history:
//   R1: 16 blocks x 256 thr, 1 float4/thr  -> 4.863999 us
//   R2: native memset node                 -> 4.863999 us (identical -> replay floor)
//   R3: 1 block x 1024 thr, 4 float4/thr   -> 6.66 us (LSU-serialized on one SM; regression)
// Conclusion: spread stores wide, one store per thread, return to the floor.

__global__ __launch_bounds__(128, 1)
void zero_wide(float4* __restrict__ out) {
    // 32 blocks x 128 threads = 4096 threads = 4096 float4 = 16384 floats.
    out[blockIdx.x * 128 + threadIdx.x] = make_float4(0.f, 0.f, 0.f, 0.f);
}

__global__ void zero_generic(float* __restrict__ out, int n) {
    int i = blockIdx.x * blockDim.x + threadIdx.x;
    if (i < n) out[i] = 0.f;
}

extern "C" void kernel_launch(void* const* d_in, const int* in_sizes, int n_in,
                              void* d_out, int out_size) {
    (void)d_in; (void)in_sizes; (void)n_in;
    if (out_size == 16384) {
        zero_wide<<<32, 128>>>((float4*)d_out);
    } else {
        int threads = 256;
        int blocks = (out_size + threads - 1) / threads;
        zero_generic<<<blocks, threads>>>((float*)d_out, out_size);
    }
}